// round 13
// baseline (speedup 1.0000x reference)
#include <cuda_runtime.h>
#include <math_constants.h>

// x [B=32, C=256, H=64, W=64] fp32
#define B    32
#define C    256
#define HW   4096
#define W64  64

// ---- k1 tiling (measured optimum; frozen) ----
#define K1T    128             // threads/block
#define HWT    512             // hw floats per block tile (128 float4)
#define NHWT   (HW / HWT)      // 8
#define CR     64              // channels per block
#define NCR    (C / CR)        // 4
#define CHUNK  4
#define NCHUNK (CR / CHUNK)    // 16

// ---- scratch (device globals; allocation-free) ----
__device__ float  g_cpart[B * NHWT * C];     // per-(b,c,hw-tile) partial sums
__device__ float4 g_pmax[NCR][B * HW / 4];   // per-c-range max partials
__device__ float4 g_psum[NCR][B * HW / 4];   // per-c-range sum partials
__device__ float  g_chw[B * C];              // channel weight
__device__ float4 g_sp4[B * HW / 4];         // spatial weight

// =====================================================================
// k1: single sweep over x. block=(cr,ht,b), 1024 CTAs.
// Register-prefetched 4-channel chunks; smem transpose for per-c sums.
// =====================================================================
__global__ __launch_bounds__(K1T) void k1_reduce(const float* __restrict__ x)
{
    const int cr   = blockIdx.x;
    const int ht   = blockIdx.y;
    const int b    = blockIdx.z;
    const int tid  = threadIdx.x;
    const int warp = tid >> 5;
    const int lane = tid & 31;

    __shared__ float sbuf[2][CHUNK][K1T];

    const float4* __restrict__ xp =
        (const float4*)x + ((long)(b * C + cr * CR) * HW + ht * HWT) / 4 + tid;

    float4 mx = make_float4(-CUDART_INF_F, -CUDART_INF_F, -CUDART_INF_F, -CUDART_INF_F);
    float4 sm = make_float4(0.f, 0.f, 0.f, 0.f);

    float4 p[CHUNK];
    #pragma unroll
    for (int j = 0; j < CHUNK; ++j) p[j] = xp[j * (HW / 4)];

    #pragma unroll 2
    for (int ch = 0; ch < NCHUNK; ++ch) {
        float4 v[CHUNK];
        #pragma unroll
        for (int j = 0; j < CHUNK; ++j) v[j] = p[j];

        // stage per-thread channel sums, then kick off next chunk's loads
        float (*sb)[K1T] = sbuf[ch & 1];
        #pragma unroll
        for (int j = 0; j < CHUNK; ++j)
            sb[j][tid] = (v[j].x + v[j].y) + (v[j].z + v[j].w);

        if (ch + 1 < NCHUNK) {
            #pragma unroll
            for (int j = 0; j < CHUNK; ++j)
                p[j] = xp[((ch + 1) * CHUNK + j) * (HW / 4)];
        }

        #pragma unroll
        for (int j = 0; j < CHUNK; ++j) {
            mx.x = fmaxf(mx.x, v[j].x); mx.y = fmaxf(mx.y, v[j].y);
            mx.z = fmaxf(mx.z, v[j].z); mx.w = fmaxf(mx.w, v[j].w);
            sm.x += v[j].x; sm.y += v[j].y; sm.z += v[j].z; sm.w += v[j].w;
        }

        __syncthreads();
        // warp w reduces channel ch*4+w over all 128 threads (stride-32: conflict-free)
        float r = (sb[warp][lane]      + sb[warp][lane + 32])
                + (sb[warp][lane + 64] + sb[warp][lane + 96]);
        r += __shfl_xor_sync(0xffffffffu, r, 16);
        r += __shfl_xor_sync(0xffffffffu, r, 8);
        r += __shfl_xor_sync(0xffffffffu, r, 4);
        r += __shfl_xor_sync(0xffffffffu, r, 2);
        r += __shfl_xor_sync(0xffffffffu, r, 1);
        if (lane == 0)
            g_cpart[(b * NHWT + ht) * C + cr * CR + ch * CHUNK + warp] = r;
    }

    const int o = b * (HW / 4) + ht * (HWT / 4) + tid;
    g_pmax[cr][o] = mx;
    g_psum[cr][o] = sm;
}

// =====================================================================
// k23: fused channel-weight (blocks 0..31) and spatial-weight (32..159).
// =====================================================================
#define SMAX_OFF 0
#define SAVG_OFF (22 * 72)
#define SW_OFF   (2 * 22 * 72)
#define SB_OFF   (SW_OFF + 98)

__global__ __launch_bounds__(256) void k23(const float* __restrict__ w1d,
                                           const float* __restrict__ w2d,
                                           const float* __restrict__ bias)
{
    __shared__ float sbig[SB_OFF + 1];
    const int tid = threadIdx.x;

    if (blockIdx.x < B) {
        // ---- channel weight: mean -> conv1d(5, pad 2) -> sigmoid ----
        const int b = blockIdx.x;
        const int c = tid;
        float acc = 0.f;
        #pragma unroll
        for (int ht = 0; ht < NHWT; ++ht)
            acc += g_cpart[(b * NHWT + ht) * C + c];
        sbig[c] = acc * (1.0f / (float)HW);
        __syncthreads();
        float y = 0.f;
        #pragma unroll
        for (int k = 0; k < 5; ++k) {
            int cc = c - 2 + k;
            float m = (cc >= 0 && cc < C) ? sbig[cc] : 0.f;
            y += w1d[k] * m;
        }
        g_chw[b * C + c] = 1.0f / (1.0f + expf(-y));
    } else {
        // ---- spatial weight: pools -> conv2d(7x7, pad 3) -> sigmoid ----
        const int idx = blockIdx.x - B;
        const int b   = idx >> 2;
        const int r0  = (idx & 3) * 16;

        float* smax = sbig + SMAX_OFF;   // [22][72]
        float* savg = sbig + SAVG_OFF;   // [22][72]
        float* sw   = sbig + SW_OFF;     // [98]

        for (int i = tid; i < 22 * 70; i += 256) {
            int rr = i / 70, cc = i % 70;
            int gr = r0 - 3 + rr, gc = cc - 3;
            float mv = 0.f, av = 0.f;
            if (gr >= 0 && gr < W64 && gc >= 0 && gc < W64) {
                int gi = b * HW + gr * W64 + gc;
                mv = -CUDART_INF_F;
                #pragma unroll
                for (int r = 0; r < NCR; ++r) {
                    mv = fmaxf(mv, ((const float*)g_pmax[r])[gi]);
                    av += ((const float*)g_psum[r])[gi];
                }
                av *= (1.0f / (float)C);
            }
            smax[rr * 72 + cc] = mv;
            savg[rr * 72 + cc] = av;
        }
        if (tid < 98) sw[tid] = w2d[tid];
        if (tid == 0) sbig[SB_OFF] = bias[0];
        __syncthreads();

        float* __restrict__ sp = (float*)g_sp4;
        #pragma unroll
        for (int k = 0; k < 4; ++k) {
            int oi   = tid + k * 256;
            int orow = oi >> 6;
            int ocol = oi & 63;
            float acc = sbig[SB_OFF];
            #pragma unroll
            for (int kh = 0; kh < 7; ++kh) {
                #pragma unroll
                for (int kw = 0; kw < 7; ++kw) {
                    acc += sw[kh * 7 + kw]      * smax[(orow + kh) * 72 + ocol + kw];
                    acc += sw[49 + kh * 7 + kw] * savg[(orow + kh) * 72 + ocol + kw];
                }
            }
            sp[b * HW + (r0 + orow) * W64 + ocol] = 1.0f / (1.0f + expf(-acc));
        }
    }
}

// =====================================================================
// k4: out = x * (chw[b,c] + sp[b,hw] + 1).
//     One CTA per PAIR of (b,c) rows (same b): 512 threads, each thread
//     loads sp once (2 float4) and applies it to both rows (4 x-loads,
//     4 stores). Reversed block order + evict-first stores.
// =====================================================================
__global__ __launch_bounds__(512) void k4_scale(const float4* __restrict__ x4,
                                                float4* __restrict__ out4)
{
    const int pair = (B * C / 2 - 1) - blockIdx.x;   // reversed: tail of x first
    const int bc0  = pair * 2;                       // even; bc0+1 shares b
    const int b    = bc0 >> 8;
    const int tid  = threadIdx.x;

    const float cw0 = g_chw[bc0]     + 1.0f;
    const float cw1 = g_chw[bc0 + 1] + 1.0f;

    const int r0    = bc0 * 1024;                    // row 0 base (float4)
    const int r1    = r0 + 1024;                     // row 1 base
    const int sbase = b * 1024;

    // sp loaded once, reused for both rows
    const float4 s0 = g_sp4[sbase + tid];
    const float4 s1 = g_sp4[sbase + tid + 512];

    const float4 v00 = x4[r0 + tid];
    const float4 v01 = x4[r0 + tid + 512];
    const float4 v10 = x4[r1 + tid];
    const float4 v11 = x4[r1 + tid + 512];

    float4 o;
    o.x = v00.x * (cw0 + s0.x); o.y = v00.y * (cw0 + s0.y);
    o.z = v00.z * (cw0 + s0.z); o.w = v00.w * (cw0 + s0.w);
    __stcs(&out4[r0 + tid], o);

    o.x = v01.x * (cw0 + s1.x); o.y = v01.y * (cw0 + s1.y);
    o.z = v01.z * (cw0 + s1.z); o.w = v01.w * (cw0 + s1.w);
    __stcs(&out4[r0 + tid + 512], o);

    o.x = v10.x * (cw1 + s0.x); o.y = v10.y * (cw1 + s0.y);
    o.z = v10.z * (cw1 + s0.z); o.w = v10.w * (cw1 + s0.w);
    __stcs(&out4[r1 + tid], o);

    o.x = v11.x * (cw1 + s1.x); o.y = v11.y * (cw1 + s1.y);
    o.z = v11.z * (cw1 + s1.z); o.w = v11.w * (cw1 + s1.w);
    __stcs(&out4[r1 + tid + 512], o);
}

// =====================================================================
extern "C" void kernel_launch(void* const* d_in, const int* in_sizes, int n_in,
                              void* d_out, int out_size)
{
    const float* x    = (const float*)d_in[0];  // [32,256,64,64]
    const float* w1d  = (const float*)d_in[1];  // [1,1,5]
    const float* w2d  = (const float*)d_in[2];  // [1,2,7,7]
    const float* bias = (const float*)d_in[3];  // [1]
    float* out = (float*)d_out;

    dim3 g1(NCR, NHWT, B);
    k1_reduce<<<g1, K1T>>>(x);
    k23<<<B + B * 4, 256>>>(w1d, w2d, bias);
    k4_scale<<<B * C / 2, 512>>>((const float4*)x, (float4*)out);
}

// round 14
// speedup vs baseline: 1.0218x; 1.0218x over previous
#include <cuda_runtime.h>
#include <math_constants.h>

// x [B=32, C=256, H=64, W=64] fp32
#define B    32
#define C    256
#define HW   4096
#define W64  64

// ---- k1 tiling (measured optimum; frozen) ----
#define K1T    128
#define HWT    512
#define NHWT   (HW / HWT)      // 8
#define CR     64
#define NCR    (C / CR)        // 4
#define CHUNK  4
#define NCHUNK (CR / CHUNK)    // 16

// ---- scratch (device globals; allocation-free) ----
__device__ float  g_cpart[B * NHWT * C];
__device__ float4 g_pmax[NCR][B * HW / 4];
__device__ float4 g_psum[NCR][B * HW / 4];
__device__ float  g_chw[B * C];
__device__ float4 g_sp4[B * HW / 4];

// =====================================================================
// k1: single sweep over x. block=(cr,ht,b), 1024 CTAs.  (round-11 exact)
// =====================================================================
__global__ __launch_bounds__(K1T) void k1_reduce(const float* __restrict__ x)
{
    const int cr   = blockIdx.x;
    const int ht   = blockIdx.y;
    const int b    = blockIdx.z;
    const int tid  = threadIdx.x;
    const int warp = tid >> 5;
    const int lane = tid & 31;

    __shared__ float sbuf[2][CHUNK][K1T];

    const float4* __restrict__ xp =
        (const float4*)x + ((long)(b * C + cr * CR) * HW + ht * HWT) / 4 + tid;

    float4 mx = make_float4(-CUDART_INF_F, -CUDART_INF_F, -CUDART_INF_F, -CUDART_INF_F);
    float4 sm = make_float4(0.f, 0.f, 0.f, 0.f);

    float4 p[CHUNK];
    #pragma unroll
    for (int j = 0; j < CHUNK; ++j) p[j] = xp[j * (HW / 4)];

    #pragma unroll 2
    for (int ch = 0; ch < NCHUNK; ++ch) {
        float4 v[CHUNK];
        #pragma unroll
        for (int j = 0; j < CHUNK; ++j) v[j] = p[j];

        float (*sb)[K1T] = sbuf[ch & 1];
        #pragma unroll
        for (int j = 0; j < CHUNK; ++j)
            sb[j][tid] = (v[j].x + v[j].y) + (v[j].z + v[j].w);

        if (ch + 1 < NCHUNK) {
            #pragma unroll
            for (int j = 0; j < CHUNK; ++j)
                p[j] = xp[((ch + 1) * CHUNK + j) * (HW / 4)];
        }

        #pragma unroll
        for (int j = 0; j < CHUNK; ++j) {
            mx.x = fmaxf(mx.x, v[j].x); mx.y = fmaxf(mx.y, v[j].y);
            mx.z = fmaxf(mx.z, v[j].z); mx.w = fmaxf(mx.w, v[j].w);
            sm.x += v[j].x; sm.y += v[j].y; sm.z += v[j].z; sm.w += v[j].w;
        }

        __syncthreads();
        float r = (sb[warp][lane]      + sb[warp][lane + 32])
                + (sb[warp][lane + 64] + sb[warp][lane + 96]);
        r += __shfl_xor_sync(0xffffffffu, r, 16);
        r += __shfl_xor_sync(0xffffffffu, r, 8);
        r += __shfl_xor_sync(0xffffffffu, r, 4);
        r += __shfl_xor_sync(0xffffffffu, r, 2);
        r += __shfl_xor_sync(0xffffffffu, r, 1);
        if (lane == 0)
            g_cpart[(b * NHWT + ht) * C + cr * CR + ch * CHUNK + warp] = r;
    }

    const int o = b * (HW / 4) + ht * (HWT / 4) + tid;
    g_pmax[cr][o] = mx;
    g_psum[cr][o] = sm;
}

// =====================================================================
// k23: fused channel-weight (blocks 0..31) and spatial-weight (32..159).
//      PDL: sync on k1 completion before touching its outputs.
// =====================================================================
#define SMAX_OFF 0
#define SAVG_OFF (22 * 72)
#define SW_OFF   (2 * 22 * 72)
#define SB_OFF   (SW_OFF + 98)

__global__ __launch_bounds__(256) void k23(const float* __restrict__ w1d,
                                           const float* __restrict__ w2d,
                                           const float* __restrict__ bias)
{
    __shared__ float sbig[SB_OFF + 1];
    const int tid = threadIdx.x;

    // weights/bias are kernel inputs, independent of k1 -> load pre-sync
    float wreg = (blockIdx.x >= B && tid < 98) ? w2d[tid] : 0.f;
    float breg = (tid == 0) ? bias[0] : 0.f;

    cudaGridDependencySynchronize();   // wait for k1's g_cpart/g_pmax/g_psum

    if (blockIdx.x < B) {
        const int b = blockIdx.x;
        const int c = tid;
        float acc = 0.f;
        #pragma unroll
        for (int ht = 0; ht < NHWT; ++ht)
            acc += g_cpart[(b * NHWT + ht) * C + c];
        sbig[c] = acc * (1.0f / (float)HW);
        __syncthreads();
        float y = 0.f;
        #pragma unroll
        for (int k = 0; k < 5; ++k) {
            int cc = c - 2 + k;
            float m = (cc >= 0 && cc < C) ? sbig[cc] : 0.f;
            y += w1d[k] * m;
        }
        g_chw[b * C + c] = 1.0f / (1.0f + expf(-y));
    } else {
        const int idx = blockIdx.x - B;
        const int b   = idx >> 2;
        const int r0  = (idx & 3) * 16;

        float* smax = sbig + SMAX_OFF;   // [22][72]
        float* savg = sbig + SAVG_OFF;   // [22][72]
        float* sw   = sbig + SW_OFF;     // [98]

        for (int i = tid; i < 22 * 70; i += 256) {
            int rr = i / 70, cc = i % 70;
            int gr = r0 - 3 + rr, gc = cc - 3;
            float mv = 0.f, av = 0.f;
            if (gr >= 0 && gr < W64 && gc >= 0 && gc < W64) {
                int gi = b * HW + gr * W64 + gc;
                mv = -CUDART_INF_F;
                #pragma unroll
                for (int r = 0; r < NCR; ++r) {
                    mv = fmaxf(mv, ((const float*)g_pmax[r])[gi]);
                    av += ((const float*)g_psum[r])[gi];
                }
                av *= (1.0f / (float)C);
            }
            smax[rr * 72 + cc] = mv;
            savg[rr * 72 + cc] = av;
        }
        if (tid < 98) sw[tid] = wreg;
        if (tid == 0) sbig[SB_OFF] = breg;
        __syncthreads();

        float* __restrict__ sp = (float*)g_sp4;
        #pragma unroll
        for (int k = 0; k < 4; ++k) {
            int oi   = tid + k * 256;
            int orow = oi >> 6;
            int ocol = oi & 63;
            float acc = sbig[SB_OFF];
            #pragma unroll
            for (int kh = 0; kh < 7; ++kh) {
                #pragma unroll
                for (int kw = 0; kw < 7; ++kw) {
                    acc += sw[kh * 7 + kw]      * smax[(orow + kh) * 72 + ocol + kw];
                    acc += sw[49 + kh * 7 + kw] * savg[(orow + kh) * 72 + ocol + kw];
                }
            }
            sp[b * HW + (r0 + orow) * W64 + ocol] = 1.0f / (1.0f + expf(-acc));
        }
    }
}

// =====================================================================
// k4: out = x * (chw[b,c] + sp[b,hw] + 1).  (round-11 shape)
//     PDL: x-loads issued BEFORE the grid-dependency sync so the read
//     front overlaps k23 (and k1's tail); weights read after sync.
// =====================================================================
__global__ __launch_bounds__(512) void k4_scale(const float4* __restrict__ x4,
                                                float4* __restrict__ out4)
{
    const int bc  = (B * C - 1) - blockIdx.x;      // reversed: tail of x first
    const int b   = bc >> 8;
    const int tid = threadIdx.x;

    const int rbase = bc * 1024;                   // this (b,c) row, in float4
    const int sbase = b * 1024;

    // x is a kernel input -> safe to load before the dependency sync
    const float4 v0 = x4[rbase + tid];
    const float4 v1 = x4[rbase + tid + 512];

    cudaGridDependencySynchronize();               // wait for k23's weights

    const float  cw = g_chw[bc] + 1.0f;
    const float4 s0 = g_sp4[sbase + tid];
    const float4 s1 = g_sp4[sbase + tid + 512];

    float4 o0, o1;
    o0.x = v0.x * (cw + s0.x);
    o0.y = v0.y * (cw + s0.y);
    o0.z = v0.z * (cw + s0.z);
    o0.w = v0.w * (cw + s0.w);
    o1.x = v1.x * (cw + s1.x);
    o1.y = v1.y * (cw + s1.y);
    o1.z = v1.z * (cw + s1.z);
    o1.w = v1.w * (cw + s1.w);

    __stcs(&out4[rbase + tid],       o0);
    __stcs(&out4[rbase + tid + 512], o1);
}

// =====================================================================
extern "C" void kernel_launch(void* const* d_in, const int* in_sizes, int n_in,
                              void* d_out, int out_size)
{
    const float* x    = (const float*)d_in[0];  // [32,256,64,64]
    const float* w1d  = (const float*)d_in[1];  // [1,1,5]
    const float* w2d  = (const float*)d_in[2];  // [1,2,7,7]
    const float* bias = (const float*)d_in[3];  // [1]
    float* out = (float*)d_out;

    dim3 g1(NCR, NHWT, B);
    k1_reduce<<<g1, K1T>>>(x);

    cudaLaunchAttribute pdl[1];
    pdl[0].id = cudaLaunchAttributeProgrammaticStreamSerialization;
    pdl[0].val.programmaticStreamSerializationAllowed = 1;

    {   // k23 with PDL (overlaps k1 tail)
        cudaLaunchConfig_t cfg = {};
        cfg.gridDim  = dim3(B + B * 4, 1, 1);
        cfg.blockDim = dim3(256, 1, 1);
        cfg.stream   = 0;
        cfg.attrs    = pdl;
        cfg.numAttrs = 1;
        cudaLaunchKernelEx(&cfg, k23, w1d, w2d, bias);
    }
    {   // k4 with PDL (x-read front overlaps k23)
        cudaLaunchConfig_t cfg = {};
        cfg.gridDim  = dim3(B * C, 1, 1);
        cfg.blockDim = dim3(512, 1, 1);
        cfg.stream   = 0;
        cfg.attrs    = pdl;
        cfg.numAttrs = 1;
        cudaLaunchKernelEx(&cfg, k4_scale, (const float4*)x, (float4*)out);
    }
}

// round 15
// speedup vs baseline: 1.0242x; 1.0023x over previous
#include <cuda_runtime.h>
#include <math_constants.h>

// x [B=32, C=256, H=64, W=64] fp32
#define B    32
#define C    256
#define HW   4096
#define W64  64

// ---- k1 tiling (measured optimum; frozen) ----
#define K1T    128
#define HWT    512
#define NHWT   (HW / HWT)      // 8
#define CR     64
#define NCR    (C / CR)        // 4
#define CHUNK  4
#define NCHUNK (CR / CHUNK)    // 16

// ---- scratch (device globals; allocation-free) ----
__device__ float  g_cpart[B * NHWT * C];
__device__ float4 g_pmax[NCR][B * HW / 4];
__device__ float4 g_psum[NCR][B * HW / 4];
__device__ float  g_chw[B * C];
__device__ float4 g_sp4[B * HW / 4];

// =====================================================================
// k1: single sweep over x. block=(cr,ht,b), 1024 CTAs.  (round-11 exact)
//     PDL: triggers dependent launch right after its last global store.
// =====================================================================
__global__ __launch_bounds__(K1T) void k1_reduce(const float* __restrict__ x)
{
    const int cr   = blockIdx.x;
    const int ht   = blockIdx.y;
    const int b    = blockIdx.z;
    const int tid  = threadIdx.x;
    const int warp = tid >> 5;
    const int lane = tid & 31;

    __shared__ float sbuf[2][CHUNK][K1T];

    const float4* __restrict__ xp =
        (const float4*)x + ((long)(b * C + cr * CR) * HW + ht * HWT) / 4 + tid;

    float4 mx = make_float4(-CUDART_INF_F, -CUDART_INF_F, -CUDART_INF_F, -CUDART_INF_F);
    float4 sm = make_float4(0.f, 0.f, 0.f, 0.f);

    float4 p[CHUNK];
    #pragma unroll
    for (int j = 0; j < CHUNK; ++j) p[j] = xp[j * (HW / 4)];

    #pragma unroll 2
    for (int ch = 0; ch < NCHUNK; ++ch) {
        float4 v[CHUNK];
        #pragma unroll
        for (int j = 0; j < CHUNK; ++j) v[j] = p[j];

        float (*sb)[K1T] = sbuf[ch & 1];
        #pragma unroll
        for (int j = 0; j < CHUNK; ++j)
            sb[j][tid] = (v[j].x + v[j].y) + (v[j].z + v[j].w);

        if (ch + 1 < NCHUNK) {
            #pragma unroll
            for (int j = 0; j < CHUNK; ++j)
                p[j] = xp[((ch + 1) * CHUNK + j) * (HW / 4)];
        }

        #pragma unroll
        for (int j = 0; j < CHUNK; ++j) {
            mx.x = fmaxf(mx.x, v[j].x); mx.y = fmaxf(mx.y, v[j].y);
            mx.z = fmaxf(mx.z, v[j].z); mx.w = fmaxf(mx.w, v[j].w);
            sm.x += v[j].x; sm.y += v[j].y; sm.z += v[j].z; sm.w += v[j].w;
        }

        __syncthreads();
        float r = (sb[warp][lane]      + sb[warp][lane + 32])
                + (sb[warp][lane + 64] + sb[warp][lane + 96]);
        r += __shfl_xor_sync(0xffffffffu, r, 16);
        r += __shfl_xor_sync(0xffffffffu, r, 8);
        r += __shfl_xor_sync(0xffffffffu, r, 4);
        r += __shfl_xor_sync(0xffffffffu, r, 2);
        r += __shfl_xor_sync(0xffffffffu, r, 1);
        if (lane == 0)
            g_cpart[(b * NHWT + ht) * C + cr * CR + ch * CHUNK + warp] = r;
    }

    const int o = b * (HW / 4) + ht * (HWT / 4) + tid;
    g_pmax[cr][o] = mx;
    g_psum[cr][o] = sm;

    __threadfence();
    cudaTriggerProgrammaticLaunchCompletion();   // let k23 launch now
}

// =====================================================================
// k23: fused channel-weight (blocks 0..31) and spatial-weight (32..159).
//      PDL: sync on k1's trigger before touching its outputs; trigger
//      k4 right after this CTA's weight stores.
// =====================================================================
#define SMAX_OFF 0
#define SAVG_OFF (22 * 72)
#define SW_OFF   (2 * 22 * 72)
#define SB_OFF   (SW_OFF + 98)

__global__ __launch_bounds__(256) void k23(const float* __restrict__ w1d,
                                           const float* __restrict__ w2d,
                                           const float* __restrict__ bias)
{
    __shared__ float sbig[SB_OFF + 1];
    const int tid = threadIdx.x;

    // weights/bias are kernel inputs, independent of k1 -> load pre-sync
    float wreg = (blockIdx.x >= B && tid < 98) ? w2d[tid] : 0.f;
    float breg = (tid == 0) ? bias[0] : 0.f;

    cudaGridDependencySynchronize();   // wait for k1's g_cpart/g_pmax/g_psum

    if (blockIdx.x < B) {
        const int b = blockIdx.x;
        const int c = tid;
        float acc = 0.f;
        #pragma unroll
        for (int ht = 0; ht < NHWT; ++ht)
            acc += g_cpart[(b * NHWT + ht) * C + c];
        sbig[c] = acc * (1.0f / (float)HW);
        __syncthreads();
        float y = 0.f;
        #pragma unroll
        for (int k = 0; k < 5; ++k) {
            int cc = c - 2 + k;
            float m = (cc >= 0 && cc < C) ? sbig[cc] : 0.f;
            y += w1d[k] * m;
        }
        g_chw[b * C + c] = 1.0f / (1.0f + expf(-y));
    } else {
        const int idx = blockIdx.x - B;
        const int b   = idx >> 2;
        const int r0  = (idx & 3) * 16;

        float* smax = sbig + SMAX_OFF;   // [22][72]
        float* savg = sbig + SAVG_OFF;   // [22][72]
        float* sw   = sbig + SW_OFF;     // [98]

        for (int i = tid; i < 22 * 70; i += 256) {
            int rr = i / 70, cc = i % 70;
            int gr = r0 - 3 + rr, gc = cc - 3;
            float mv = 0.f, av = 0.f;
            if (gr >= 0 && gr < W64 && gc >= 0 && gc < W64) {
                int gi = b * HW + gr * W64 + gc;
                mv = -CUDART_INF_F;
                #pragma unroll
                for (int r = 0; r < NCR; ++r) {
                    mv = fmaxf(mv, ((const float*)g_pmax[r])[gi]);
                    av += ((const float*)g_psum[r])[gi];
                }
                av *= (1.0f / (float)C);
            }
            smax[rr * 72 + cc] = mv;
            savg[rr * 72 + cc] = av;
        }
        if (tid < 98) sw[tid] = wreg;
        if (tid == 0) sbig[SB_OFF] = breg;
        __syncthreads();

        float* __restrict__ sp = (float*)g_sp4;
        #pragma unroll
        for (int k = 0; k < 4; ++k) {
            int oi   = tid + k * 256;
            int orow = oi >> 6;
            int ocol = oi & 63;
            float acc = sbig[SB_OFF];
            #pragma unroll
            for (int kh = 0; kh < 7; ++kh) {
                #pragma unroll
                for (int kw = 0; kw < 7; ++kw) {
                    acc += sw[kh * 7 + kw]      * smax[(orow + kh) * 72 + ocol + kw];
                    acc += sw[49 + kh * 7 + kw] * savg[(orow + kh) * 72 + ocol + kw];
                }
            }
            sp[b * HW + (r0 + orow) * W64 + ocol] = 1.0f / (1.0f + expf(-acc));
        }
    }

    __threadfence();
    cudaTriggerProgrammaticLaunchCompletion();   // let k4 launch now
}

// =====================================================================
// k4: out = x * (chw[b,c] + sp[b,hw] + 1).  (round-11 shape)
//     PDL: x-loads issued BEFORE the grid-dependency sync so the read
//     front overlaps k23 (and k1's retirement); weights read after sync.
// =====================================================================
__global__ __launch_bounds__(512) void k4_scale(const float4* __restrict__ x4,
                                                float4* __restrict__ out4)
{
    const int bc  = (B * C - 1) - blockIdx.x;      // reversed: tail of x first
    const int b   = bc >> 8;
    const int tid = threadIdx.x;

    const int rbase = bc * 1024;                   // this (b,c) row, in float4
    const int sbase = b * 1024;

    // x is a kernel input -> safe to load before the dependency sync
    const float4 v0 = x4[rbase + tid];
    const float4 v1 = x4[rbase + tid + 512];

    cudaGridDependencySynchronize();               // wait for k23's weights

    const float  cw = g_chw[bc] + 1.0f;
    const float4 s0 = g_sp4[sbase + tid];
    const float4 s1 = g_sp4[sbase + tid + 512];

    float4 o0, o1;
    o0.x = v0.x * (cw + s0.x);
    o0.y = v0.y * (cw + s0.y);
    o0.z = v0.z * (cw + s0.z);
    o0.w = v0.w * (cw + s0.w);
    o1.x = v1.x * (cw + s1.x);
    o1.y = v1.y * (cw + s1.y);
    o1.z = v1.z * (cw + s1.z);
    o1.w = v1.w * (cw + s1.w);

    __stcs(&out4[rbase + tid],       o0);
    __stcs(&out4[rbase + tid + 512], o1);
}

// =====================================================================
extern "C" void kernel_launch(void* const* d_in, const int* in_sizes, int n_in,
                              void* d_out, int out_size)
{
    const float* x    = (const float*)d_in[0];  // [32,256,64,64]
    const float* w1d  = (const float*)d_in[1];  // [1,1,5]
    const float* w2d  = (const float*)d_in[2];  // [1,2,7,7]
    const float* bias = (const float*)d_in[3];  // [1]
    float* out = (float*)d_out;

    dim3 g1(NCR, NHWT, B);
    k1_reduce<<<g1, K1T>>>(x);

    cudaLaunchAttribute pdl[1];
    pdl[0].id = cudaLaunchAttributeProgrammaticStreamSerialization;
    pdl[0].val.programmaticStreamSerializationAllowed = 1;

    {   // k23 with PDL (overlaps k1 retirement tail)
        cudaLaunchConfig_t cfg = {};
        cfg.gridDim  = dim3(B + B * 4, 1, 1);
        cfg.blockDim = dim3(256, 1, 1);
        cfg.stream   = 0;
        cfg.attrs    = pdl;
        cfg.numAttrs = 1;
        cudaLaunchKernelEx(&cfg, k23, w1d, w2d, bias);
    }
    {   // k4 with PDL (x-read front overlaps k23)
        cudaLaunchConfig_t cfg = {};
        cfg.gridDim  = dim3(B * C, 1, 1);
        cfg.blockDim = dim3(512, 1, 1);
        cfg.stream   = 0;
        cfg.attrs    = pdl;
        cfg.numAttrs = 1;
        cudaLaunchKernelEx(&cfg, k4_scale, (const float4*)x, (float4*)out);
    }
}

// round 16
// speedup vs baseline: 1.0251x; 1.0009x over previous
#include <cuda_runtime.h>
#include <math_constants.h>

// x [B=32, C=256, H=64, W=64] fp32
#define B    32
#define C    256
#define HW   4096
#define W64  64

// ---- k1 tiling (measured optimum; frozen) ----
#define K1T    128
#define HWT    512
#define NHWT   (HW / HWT)      // 8
#define CR     64
#define NCR    (C / CR)        // 4
#define CHUNK  4
#define NCHUNK (CR / CHUNK)    // 16

// ---- scratch (device globals; allocation-free) ----
__device__ float  g_cpart[B * NHWT * C];
__device__ float4 g_pmax[NCR][B * HW / 4];
__device__ float4 g_psum[NCR][B * HW / 4];
__device__ float  g_chw[B * C];
__device__ float4 g_sp4[B * HW / 4];

// =====================================================================
// k1: single sweep over x. block=(cr,ht,b), 1024 CTAs.
//     Depth-4 register prefetch; unroll-4 chunk loop lets ptxas pipeline
//     loads across chunk bodies. PDL trigger after final stores.
// =====================================================================
__global__ __launch_bounds__(K1T) void k1_reduce(const float* __restrict__ x)
{
    const int cr   = blockIdx.x;
    const int ht   = blockIdx.y;
    const int b    = blockIdx.z;
    const int tid  = threadIdx.x;
    const int warp = tid >> 5;
    const int lane = tid & 31;

    __shared__ float sbuf[2][CHUNK][K1T];

    const float4* __restrict__ xp =
        (const float4*)x + ((long)(b * C + cr * CR) * HW + ht * HWT) / 4 + tid;

    float4 mx = make_float4(-CUDART_INF_F, -CUDART_INF_F, -CUDART_INF_F, -CUDART_INF_F);
    float4 sm = make_float4(0.f, 0.f, 0.f, 0.f);

    float4 p[CHUNK];
    #pragma unroll
    for (int j = 0; j < CHUNK; ++j) p[j] = xp[j * (HW / 4)];

    #pragma unroll 4
    for (int ch = 0; ch < NCHUNK; ++ch) {
        float4 v[CHUNK];
        #pragma unroll
        for (int j = 0; j < CHUNK; ++j) v[j] = p[j];

        float (*sb)[K1T] = sbuf[ch & 1];
        #pragma unroll
        for (int j = 0; j < CHUNK; ++j)
            sb[j][tid] = (v[j].x + v[j].y) + (v[j].z + v[j].w);

        if (ch + 1 < NCHUNK) {
            #pragma unroll
            for (int j = 0; j < CHUNK; ++j)
                p[j] = xp[((ch + 1) * CHUNK + j) * (HW / 4)];
        }

        #pragma unroll
        for (int j = 0; j < CHUNK; ++j) {
            mx.x = fmaxf(mx.x, v[j].x); mx.y = fmaxf(mx.y, v[j].y);
            mx.z = fmaxf(mx.z, v[j].z); mx.w = fmaxf(mx.w, v[j].w);
            sm.x += v[j].x; sm.y += v[j].y; sm.z += v[j].z; sm.w += v[j].w;
        }

        __syncthreads();
        float r = (sb[warp][lane]      + sb[warp][lane + 32])
                + (sb[warp][lane + 64] + sb[warp][lane + 96]);
        r += __shfl_xor_sync(0xffffffffu, r, 16);
        r += __shfl_xor_sync(0xffffffffu, r, 8);
        r += __shfl_xor_sync(0xffffffffu, r, 4);
        r += __shfl_xor_sync(0xffffffffu, r, 2);
        r += __shfl_xor_sync(0xffffffffu, r, 1);
        if (lane == 0)
            g_cpart[(b * NHWT + ht) * C + cr * CR + ch * CHUNK + warp] = r;
    }

    const int o = b * (HW / 4) + ht * (HWT / 4) + tid;
    g_pmax[cr][o] = mx;
    g_psum[cr][o] = sm;

    __threadfence();
    cudaTriggerProgrammaticLaunchCompletion();   // let k23 launch now
}

// =====================================================================
// k23: fused channel-weight (blocks 0..31) and spatial-weight (32..159).
//      PDL: sync on k1 before touching its outputs; trigger k4 after.
// =====================================================================
#define SMAX_OFF 0
#define SAVG_OFF (22 * 72)
#define SW_OFF   (2 * 22 * 72)
#define SB_OFF   (SW_OFF + 98)

__global__ __launch_bounds__(256) void k23(const float* __restrict__ w1d,
                                           const float* __restrict__ w2d,
                                           const float* __restrict__ bias)
{
    __shared__ float sbig[SB_OFF + 1];
    const int tid = threadIdx.x;

    // weights/bias are kernel inputs, independent of k1 -> load pre-sync
    float wreg = (blockIdx.x >= B && tid < 98) ? w2d[tid] : 0.f;
    float breg = (tid == 0) ? bias[0] : 0.f;

    cudaGridDependencySynchronize();   // wait for k1's g_cpart/g_pmax/g_psum

    if (blockIdx.x < B) {
        const int b = blockIdx.x;
        const int c = tid;
        float acc = 0.f;
        #pragma unroll
        for (int ht = 0; ht < NHWT; ++ht)
            acc += g_cpart[(b * NHWT + ht) * C + c];
        sbig[c] = acc * (1.0f / (float)HW);
        __syncthreads();
        float y = 0.f;
        #pragma unroll
        for (int k = 0; k < 5; ++k) {
            int cc = c - 2 + k;
            float m = (cc >= 0 && cc < C) ? sbig[cc] : 0.f;
            y += w1d[k] * m;
        }
        g_chw[b * C + c] = 1.0f / (1.0f + expf(-y));
    } else {
        const int idx = blockIdx.x - B;
        const int b   = idx >> 2;
        const int r0  = (idx & 3) * 16;

        float* smax = sbig + SMAX_OFF;   // [22][72]
        float* savg = sbig + SAVG_OFF;   // [22][72]
        float* sw   = sbig + SW_OFF;     // [98]

        for (int i = tid; i < 22 * 70; i += 256) {
            int rr = i / 70, cc = i % 70;
            int gr = r0 - 3 + rr, gc = cc - 3;
            float mv = 0.f, av = 0.f;
            if (gr >= 0 && gr < W64 && gc >= 0 && gc < W64) {
                int gi = b * HW + gr * W64 + gc;
                mv = -CUDART_INF_F;
                #pragma unroll
                for (int r = 0; r < NCR; ++r) {
                    mv = fmaxf(mv, ((const float*)g_pmax[r])[gi]);
                    av += ((const float*)g_psum[r])[gi];
                }
                av *= (1.0f / (float)C);
            }
            smax[rr * 72 + cc] = mv;
            savg[rr * 72 + cc] = av;
        }
        if (tid < 98) sw[tid] = wreg;
        if (tid == 0) sbig[SB_OFF] = breg;
        __syncthreads();

        float* __restrict__ sp = (float*)g_sp4;
        #pragma unroll
        for (int k = 0; k < 4; ++k) {
            int oi   = tid + k * 256;
            int orow = oi >> 6;
            int ocol = oi & 63;
            float acc = sbig[SB_OFF];
            #pragma unroll
            for (int kh = 0; kh < 7; ++kh) {
                #pragma unroll
                for (int kw = 0; kw < 7; ++kw) {
                    acc += sw[kh * 7 + kw]      * smax[(orow + kh) * 72 + ocol + kw];
                    acc += sw[49 + kh * 7 + kw] * savg[(orow + kh) * 72 + ocol + kw];
                }
            }
            sp[b * HW + (r0 + orow) * W64 + ocol] = 1.0f / (1.0f + expf(-acc));
        }
    }

    __threadfence();
    cudaTriggerProgrammaticLaunchCompletion();   // let k4 launch now
}

// =====================================================================
// k4: out = x * (chw[b,c] + sp[b,hw] + 1).
//     One CTA per (b,c) row: 512 thr x 2 float4 (measured best shape).
//     PDL: x-loads issued before the dependency sync; reversed order;
//     evict-first stores.
// =====================================================================
__global__ __launch_bounds__(512) void k4_scale(const float4* __restrict__ x4,
                                                float4* __restrict__ out4)
{
    const int bc  = (B * C - 1) - blockIdx.x;      // reversed: tail of x first
    const int b   = bc >> 8;
    const int tid = threadIdx.x;

    const int rbase = bc * 1024;                   // this (b,c) row, in float4
    const int sbase = b * 1024;

    // x is a kernel input -> safe to load before the dependency sync
    const float4 v0 = x4[rbase + tid];
    const float4 v1 = x4[rbase + tid + 512];

    cudaGridDependencySynchronize();               // wait for k23's weights

    const float  cw = g_chw[bc] + 1.0f;
    const float4 s0 = g_sp4[sbase + tid];
    const float4 s1 = g_sp4[sbase + tid + 512];

    float4 o0, o1;
    o0.x = v0.x * (cw + s0.x);
    o0.y = v0.y * (cw + s0.y);
    o0.z = v0.z * (cw + s0.z);
    o0.w = v0.w * (cw + s0.w);
    o1.x = v1.x * (cw + s1.x);
    o1.y = v1.y * (cw + s1.y);
    o1.z = v1.z * (cw + s1.z);
    o1.w = v1.w * (cw + s1.w);

    __stcs(&out4[rbase + tid],       o0);
    __stcs(&out4[rbase + tid + 512], o1);
}

// =====================================================================
extern "C" void kernel_launch(void* const* d_in, const int* in_sizes, int n_in,
                              void* d_out, int out_size)
{
    const float* x    = (const float*)d_in[0];  // [32,256,64,64]
    const float* w1d  = (const float*)d_in[1];  // [1,1,5]
    const float* w2d  = (const float*)d_in[2];  // [1,2,7,7]
    const float* bias = (const float*)d_in[3];  // [1]
    float* out = (float*)d_out;

    dim3 g1(NCR, NHWT, B);
    k1_reduce<<<g1, K1T>>>(x);

    cudaLaunchAttribute pdl[1];
    pdl[0].id = cudaLaunchAttributeProgrammaticStreamSerialization;
    pdl[0].val.programmaticStreamSerializationAllowed = 1;

    {   // k23 with PDL (overlaps k1 retirement tail)
        cudaLaunchConfig_t cfg = {};
        cfg.gridDim  = dim3(B + B * 4, 1, 1);
        cfg.blockDim = dim3(256, 1, 1);
        cfg.stream   = 0;
        cfg.attrs    = pdl;
        cfg.numAttrs = 1;
        cudaLaunchKernelEx(&cfg, k23, w1d, w2d, bias);
    }
    {   // k4 with PDL (x-read front overlaps k23)
        cudaLaunchConfig_t cfg = {};
        cfg.gridDim  = dim3(B * C, 1, 1);
        cfg.blockDim = dim3(512, 1, 1);
        cfg.stream   = 0;
        cfg.attrs    = pdl;
        cfg.numAttrs = 1;
        cudaLaunchKernelEx(&cfg, k4_scale, (const float4*)x, (float4*)out);
    }
}